// round 2
// baseline (speedup 1.0000x reference)
#include <cuda_runtime.h>
#include <math.h>

#define WG 640      // grid "w" dimension (output dim 2)
#define HG 480      // grid "h" dimension (output dim 3, innermost)
#define IMW 640     // image width
#define IMH 480     // image height
#define MAXB 64

__device__ float g_M[MAXB][9];   // per-batch combined 3x3 (row-vector convention)
__device__ float g_C[MAXB][3];   // per-batch translation row @ K
__device__ float g_max;          // global uv max

// ---------------------------------------------------------------------------
// Setup: K^-1, per-batch folded matrices M_b = K^-1 @ T[0:3,0:3] @ K,
//        C_b = T[3,0:3] @ K, and reset the global max accumulator.
// ---------------------------------------------------------------------------
__global__ void stn_setup(const float* __restrict__ T,
                          const float* __restrict__ K, int B) {
    __shared__ float Kinv[9], Ks[9];
    int t = threadIdx.x;
    if (t == 0) {
        float a = K[0], b = K[1], c = K[2];
        float d = K[3], e = K[4], f = K[5];
        float g = K[6], h = K[7], i = K[8];
        float det = a * (e * i - f * h) - b * (d * i - f * g) + c * (d * h - e * g);
        float inv = 1.0f / det;
        Kinv[0] = (e * i - f * h) * inv; Kinv[1] = (c * h - b * i) * inv; Kinv[2] = (b * f - c * e) * inv;
        Kinv[3] = (f * g - d * i) * inv; Kinv[4] = (a * i - c * g) * inv; Kinv[5] = (c * d - a * f) * inv;
        Kinv[6] = (d * h - e * g) * inv; Kinv[7] = (b * g - a * h) * inv; Kinv[8] = (a * e - b * d) * inv;
        #pragma unroll
        for (int j = 0; j < 9; j++) Ks[j] = K[j];
        g_max = -INFINITY;
    }
    __syncthreads();
    int bi = t;
    if (bi < B) {
        const float* Tb = T + bi * 16;
        float A[9];
        #pragma unroll
        for (int r = 0; r < 3; r++)
            #pragma unroll
            for (int c = 0; c < 3; c++)
                A[r * 3 + c] = Kinv[r * 3 + 0] * Tb[0 * 4 + c]
                             + Kinv[r * 3 + 1] * Tb[1 * 4 + c]
                             + Kinv[r * 3 + 2] * Tb[2 * 4 + c];
        #pragma unroll
        for (int r = 0; r < 3; r++)
            #pragma unroll
            for (int c = 0; c < 3; c++)
                g_M[bi][r * 3 + c] = A[r * 3 + 0] * Ks[0 * 3 + c]
                                   + A[r * 3 + 1] * Ks[1 * 3 + c]
                                   + A[r * 3 + 2] * Ks[2 * 3 + c];
        #pragma unroll
        for (int c = 0; c < 3; c++)
            g_C[bi][c] = Tb[12] * Ks[c] + Tb[13] * Ks[3 + c] + Tb[14] * Ks[6 + c];
    }
}

__device__ __forceinline__ void atomicMaxFloat(float* addr, float v) {
    // IEEE-754 ordering trick; result is order-independent (deterministic).
    if (v >= 0.0f) {
        atomicMax((int*)addr, __float_as_int(v));
    } else {
        atomicMin((unsigned int*)addr, __float_as_uint(v));
    }
}

__device__ __forceinline__ void compute_uv(int b, int w, int h, float depth,
                                           float& ux, float& uy) {
    const float* M = g_M[b];
    const float* C = g_C[b];
    float fh = (float)h, fw = (float)w;
    // homo_uv = (h, w, 1) row-vector (reference's meshgrid quirk)
    float d0 = depth * (fh * M[0] + fw * M[3] + M[6]) + C[0];
    float d1 = depth * (fh * M[1] + fw * M[4] + M[7]) + C[1];
    float d2 = depth * (fh * M[2] + fw * M[5] + M[8]) + C[2];
    float den = d2 + 1e-4f;
    ux = d0 / den;
    uy = d1 / den;
}

// ---------------------------------------------------------------------------
// Pass 1: global max over all uv components
// ---------------------------------------------------------------------------
__global__ void stn_max(const float* __restrict__ depth_map, int npix) {
    int stride = gridDim.x * blockDim.x;
    float m = -INFINITY;
    for (int p = blockIdx.x * blockDim.x + threadIdx.x; p < npix; p += stride) {
        int h = p % HG;
        int w = (p / HG) % WG;
        int b = p / (HG * WG);
        float depth = depth_map[p];  // [B,W,H,1] layout == linear p
        float ux, uy;
        compute_uv(b, w, h, depth, ux, uy);
        m = fmaxf(m, fmaxf(ux, uy));
    }
    // warp reduce
    #pragma unroll
    for (int off = 16; off > 0; off >>= 1)
        m = fmaxf(m, __shfl_xor_sync(0xFFFFFFFF, m, off));
    __shared__ float sm[32];
    int lane = threadIdx.x & 31, wid = threadIdx.x >> 5;
    if (lane == 0) sm[wid] = m;
    __syncthreads();
    if (wid == 0) {
        int nw = blockDim.x >> 5;
        m = (lane < nw) ? sm[lane] : -INFINITY;
        #pragma unroll
        for (int off = 16; off > 0; off >>= 1)
            m = fmaxf(m, __shfl_xor_sync(0xFFFFFFFF, m, off));
        if (lane == 0) atomicMaxFloat(&g_max, m);
    }
}

// ---------------------------------------------------------------------------
// Pass 2: normalize + bilinear sample (zeros padding), 3 channels per thread
// ---------------------------------------------------------------------------
__global__ void stn_sample(const float* __restrict__ depth_map,
                           const float* __restrict__ image,
                           float* __restrict__ out, int npix) {
    int p = blockIdx.x * blockDim.x + threadIdx.x;
    if (p >= npix) return;
    int h = p % HG;
    int w = (p / HG) % WG;
    int b = p / (HG * WG);

    float depth = depth_map[p];
    float ux, uy;
    compute_uv(b, w, h, depth, ux, uy);

    float Mx = g_max;
    float gx = 2.0f * (ux / Mx) - 1.0f;
    float gy = 2.0f * (uy / Mx) - 1.0f;
    // grid_sample, align_corners=False
    float x = (gx + 1.0f) * (IMW * 0.5f) - 0.5f;
    float y = (gy + 1.0f) * (IMH * 0.5f) - 0.5f;
    float x0f = floorf(x), y0f = floorf(y);
    float wx = x - x0f, wy = y - y0f;
    int x0 = (int)x0f, y0 = (int)y0f;
    int x1 = x0 + 1, y1 = y0 + 1;

    const float* img = image + (size_t)b * 3 * IMH * IMW;
    const int chs = IMH * IMW;

    float acc0 = 0.0f, acc1 = 0.0f, acc2 = 0.0f;

    float w00 = (1.0f - wx) * (1.0f - wy);
    float w01 = wx * (1.0f - wy);
    float w10 = (1.0f - wx) * wy;
    float w11 = wx * wy;

    bool vx0 = (x0 >= 0) && (x0 < IMW);
    bool vx1 = (x1 >= 0) && (x1 < IMW);
    bool vy0 = (y0 >= 0) && (y0 < IMH);
    bool vy1 = (y1 >= 0) && (y1 < IMH);

    if (vy0) {
        int row = y0 * IMW;
        if (vx0) {
            int o = row + x0;
            acc0 += w00 * img[o]; acc1 += w00 * img[chs + o]; acc2 += w00 * img[2 * chs + o];
        }
        if (vx1) {
            int o = row + x1;
            acc0 += w01 * img[o]; acc1 += w01 * img[chs + o]; acc2 += w01 * img[2 * chs + o];
        }
    }
    if (vy1) {
        int row = y1 * IMW;
        if (vx0) {
            int o = row + x0;
            acc0 += w10 * img[o]; acc1 += w10 * img[chs + o]; acc2 += w10 * img[2 * chs + o];
        }
        if (vx1) {
            int o = row + x1;
            acc0 += w11 * img[o]; acc1 += w11 * img[chs + o]; acc2 += w11 * img[2 * chs + o];
        }
    }

    // out[b, c, w, h], h innermost -> coalesced
    size_t base = ((size_t)(b * 3) * WG + w) * HG + h;
    const size_t ostride = (size_t)WG * HG;
    out[base] = acc0;
    out[base + ostride] = acc1;
    out[base + 2 * ostride] = acc2;
}

extern "C" void kernel_launch(void* const* d_in, const int* in_sizes, int n_in,
                              void* d_out, int out_size) {
    const float* depth = (const float*)d_in[0];   // [B, 640, 480, 1]
    const float* trans = (const float*)d_in[1];   // [B, 4, 4]
    const float* image = (const float*)d_in[2];   // [B, 3, 480, 640]
    const float* K     = (const float*)d_in[3];   // [3, 3]
    float* out = (float*)d_out;                   // [B, 3, 640, 480]

    int B = in_sizes[0] / (WG * HG);
    int npix = B * WG * HG;

    stn_setup<<<1, 64>>>(trans, K, B);

    int threads = 256;
    int rblocks = 2048;
    stn_max<<<rblocks, threads>>>(depth, npix);

    int sblocks = (npix + threads - 1) / threads;
    stn_sample<<<sblocks, threads>>>(depth, image, out, npix);
}

// round 3
// speedup vs baseline: 1.8055x; 1.8055x over previous
#include <cuda_runtime.h>
#include <math.h>

#define WG 640      // grid "w" dimension (output dim 2)
#define HG 480      // grid "h" dimension (output dim 3, innermost)
#define IMW 640     // image width
#define IMH 480     // image height
#define MAXB 64
#define HQ (HG / 4) // float4 groups along h

__device__ float g_M[MAXB][9];   // per-batch combined 3x3 (row-vector convention)
__device__ float g_C[MAXB][3];   // per-batch translation row @ K
__device__ float g_max;          // global uv max

// ---------------------------------------------------------------------------
// Setup: K^-1, per-batch folded matrices M_b = K^-1 @ T[0:3,0:3] @ K,
//        C_b = T[3,0:3] @ K, and reset the global max accumulator.
// ---------------------------------------------------------------------------
__global__ void stn_setup(const float* __restrict__ T,
                          const float* __restrict__ K, int B) {
    __shared__ float Kinv[9], Ks[9];
    int t = threadIdx.x;
    if (t == 0) {
        float a = K[0], b = K[1], c = K[2];
        float d = K[3], e = K[4], f = K[5];
        float g = K[6], h = K[7], i = K[8];
        float det = a * (e * i - f * h) - b * (d * i - f * g) + c * (d * h - e * g);
        float inv = 1.0f / det;
        Kinv[0] = (e * i - f * h) * inv; Kinv[1] = (c * h - b * i) * inv; Kinv[2] = (b * f - c * e) * inv;
        Kinv[3] = (f * g - d * i) * inv; Kinv[4] = (a * i - c * g) * inv; Kinv[5] = (c * d - a * f) * inv;
        Kinv[6] = (d * h - e * g) * inv; Kinv[7] = (b * g - a * h) * inv; Kinv[8] = (a * e - b * d) * inv;
        #pragma unroll
        for (int j = 0; j < 9; j++) Ks[j] = K[j];
        g_max = -INFINITY;
    }
    __syncthreads();
    int bi = t;
    if (bi < B) {
        const float* Tb = T + bi * 16;
        float A[9];
        #pragma unroll
        for (int r = 0; r < 3; r++)
            #pragma unroll
            for (int c = 0; c < 3; c++)
                A[r * 3 + c] = Kinv[r * 3 + 0] * Tb[0 * 4 + c]
                             + Kinv[r * 3 + 1] * Tb[1 * 4 + c]
                             + Kinv[r * 3 + 2] * Tb[2 * 4 + c];
        #pragma unroll
        for (int r = 0; r < 3; r++)
            #pragma unroll
            for (int c = 0; c < 3; c++)
                g_M[bi][r * 3 + c] = A[r * 3 + 0] * Ks[0 * 3 + c]
                                   + A[r * 3 + 1] * Ks[1 * 3 + c]
                                   + A[r * 3 + 2] * Ks[2 * 3 + c];
        #pragma unroll
        for (int c = 0; c < 3; c++)
            g_C[bi][c] = Tb[12] * Ks[c] + Tb[13] * Ks[3 + c] + Tb[14] * Ks[6 + c];
    }
}

__device__ __forceinline__ void atomicMaxFloat(float* addr, float v) {
    if (v >= 0.0f) {
        atomicMax((int*)addr, __float_as_int(v));
    } else {
        atomicMin((unsigned int*)addr, __float_as_uint(v));
    }
}

// ---------------------------------------------------------------------------
// Pass 1: global max over all uv components (float4 over h)
// ---------------------------------------------------------------------------
__global__ void stn_max(const float4* __restrict__ depth4, int nq) {
    int stride = gridDim.x * blockDim.x;
    float m = -INFINITY;
    for (int q = blockIdx.x * blockDim.x + threadIdx.x; q < nq; q += stride) {
        int hq = q % HQ;
        int w  = (q / HQ) % WG;
        int b  = q / (HQ * WG);
        const float* M = g_M[b];
        const float* C = g_C[b];
        float fh = (float)(hq * 4), fw = (float)w;
        // row terms at base h; advance by M[0],M[1],M[2] per h step
        float t0 = fh * M[0] + fw * M[3] + M[6];
        float t1 = fh * M[1] + fw * M[4] + M[7];
        float t2 = fh * M[2] + fw * M[5] + M[8];
        float4 d4 = depth4[q];
        float dep[4] = {d4.x, d4.y, d4.z, d4.w};
        #pragma unroll
        for (int i = 0; i < 4; i++) {
            float d0 = dep[i] * t0 + C[0];
            float d1 = dep[i] * t1 + C[1];
            float d2 = dep[i] * t2 + C[2];
            float r = __fdividef(1.0f, d2 + 1e-4f);
            m = fmaxf(m, fmaxf(d0 * r, d1 * r));
            t0 += M[0]; t1 += M[1]; t2 += M[2];
        }
    }
    #pragma unroll
    for (int off = 16; off > 0; off >>= 1)
        m = fmaxf(m, __shfl_xor_sync(0xFFFFFFFF, m, off));
    __shared__ float sm[32];
    int lane = threadIdx.x & 31, wid = threadIdx.x >> 5;
    if (lane == 0) sm[wid] = m;
    __syncthreads();
    if (wid == 0) {
        int nw = blockDim.x >> 5;
        m = (lane < nw) ? sm[lane] : -INFINITY;
        #pragma unroll
        for (int off = 16; off > 0; off >>= 1)
            m = fmaxf(m, __shfl_xor_sync(0xFFFFFFFF, m, off));
        if (lane == 0) atomicMaxFloat(&g_max, m);
    }
}

// ---------------------------------------------------------------------------
// Pass 2: normalize + bilinear sample (zeros padding), 4 pixels x 3 ch/thread
// ---------------------------------------------------------------------------
__global__ void stn_sample(const float4* __restrict__ depth4,
                           const float* __restrict__ image,
                           float4* __restrict__ out4, int nq) {
    int q = blockIdx.x * blockDim.x + threadIdx.x;
    if (q >= nq) return;
    int hq = q % HQ;
    int w  = (q / HQ) % WG;
    int b  = q / (HQ * WG);

    const float* M = g_M[b];
    const float* C = g_C[b];
    float fh = (float)(hq * 4), fw = (float)w;
    float t0 = fh * M[0] + fw * M[3] + M[6];
    float t1 = fh * M[1] + fw * M[4] + M[7];
    float t2 = fh * M[2] + fw * M[5] + M[8];

    float Mx = g_max;
    // x = ux * (IMW/Mx) - 0.5 ; y = uy * (IMH/Mx) - 0.5
    float cw = __fdividef((float)IMW, Mx);
    float ch = __fdividef((float)IMH, Mx);

    float4 d4 = depth4[q];
    float dep[4] = {d4.x, d4.y, d4.z, d4.w};

    const float* img = image + (size_t)b * 3 * IMH * IMW;
    const int chs = IMH * IMW;

    float a0[4], a1[4], a2[4];

    #pragma unroll
    for (int i = 0; i < 4; i++) {
        float d0 = dep[i] * t0 + C[0];
        float d1 = dep[i] * t1 + C[1];
        float d2 = dep[i] * t2 + C[2];
        t0 += M[0]; t1 += M[1]; t2 += M[2];
        float r = __fdividef(1.0f, d2 + 1e-4f);
        float x = d0 * r * cw - 0.5f;
        float y = d1 * r * ch - 0.5f;

        float x0f = floorf(x), y0f = floorf(y);
        float wx = x - x0f, wy = y - y0f;
        int x0 = (int)x0f, y0 = (int)y0f;
        int x1 = x0 + 1, y1 = y0 + 1;

        float w00 = (1.0f - wx) * (1.0f - wy);
        float w01 = wx * (1.0f - wy);
        float w10 = (1.0f - wx) * wy;
        float w11 = wx * wy;

        bool vx0 = (x0 >= 0) && (x0 < IMW);
        bool vx1 = (x1 >= 0) && (x1 < IMW);
        bool vy0 = (y0 >= 0) && (y0 < IMH);
        bool vy1 = (y1 >= 0) && (y1 < IMH);

        float s0 = 0.0f, s1 = 0.0f, s2 = 0.0f;
        if (vy0) {
            int row = y0 * IMW;
            if (vx0) {
                int o = row + x0;
                s0 += w00 * img[o]; s1 += w00 * img[chs + o]; s2 += w00 * img[2 * chs + o];
            }
            if (vx1) {
                int o = row + x1;
                s0 += w01 * img[o]; s1 += w01 * img[chs + o]; s2 += w01 * img[2 * chs + o];
            }
        }
        if (vy1) {
            int row = y1 * IMW;
            if (vx0) {
                int o = row + x0;
                s0 += w10 * img[o]; s1 += w10 * img[chs + o]; s2 += w10 * img[2 * chs + o];
            }
            if (vx1) {
                int o = row + x1;
                s0 += w11 * img[o]; s1 += w11 * img[chs + o]; s2 += w11 * img[2 * chs + o];
            }
        }
        a0[i] = s0; a1[i] = s1; a2[i] = s2;
    }

    // out[b, c, w, h] with h innermost; float4 groups along h
    size_t base = ((size_t)(b * 3) * WG + w) * HQ + hq;  // in float4 units
    const size_t ostride = (size_t)WG * HQ;
    out4[base]               = make_float4(a0[0], a0[1], a0[2], a0[3]);
    out4[base + ostride]     = make_float4(a1[0], a1[1], a1[2], a1[3]);
    out4[base + 2 * ostride] = make_float4(a2[0], a2[1], a2[2], a2[3]);
}

extern "C" void kernel_launch(void* const* d_in, const int* in_sizes, int n_in,
                              void* d_out, int out_size) {
    const float* depth = (const float*)d_in[0];   // [B, 640, 480, 1]
    const float* trans = (const float*)d_in[1];   // [B, 4, 4]
    const float* image = (const float*)d_in[2];   // [B, 3, 480, 640]
    const float* K     = (const float*)d_in[3];   // [3, 3]
    float* out = (float*)d_out;                   // [B, 3, 640, 480]

    int B = in_sizes[0] / (WG * HG);
    int nq = B * WG * HQ;   // float4 groups

    stn_setup<<<1, 64>>>(trans, K, B);

    int threads = 256;
    int rblocks = 1184;  // 8 per SM, grid-stride
    stn_max<<<rblocks, threads>>>((const float4*)depth, nq);

    int sblocks = (nq + threads - 1) / threads;
    stn_sample<<<sblocks, threads>>>((const float4*)depth, image, (float4*)out, nq);
}